// round 14
// baseline (speedup 1.0000x reference)
#include <cuda_runtime.h>

#define SQ 2048
#define DM 1024
#define NH 16
#define DH 64

// Scratch (device globals; no allocation allowed)
__device__ float g_Q[SQ * DM];   // Q; later av partial #1
__device__ float g_K[SQ * DM];   // K; later av partial #2
__device__ float g_V[SQ * DM];
__device__ float g_C[SQ * DM];   // av partial #0
__device__ float g_P3[SQ * DM];  // av partial #3
__device__ float g_Spart[NH * SQ * 32];
__device__ float g_S[NH * SQ];

struct Proj3 {
    const float* W[3];
    const float* bias[3];
    float* C[3];
    float scale[3];
};
struct ASrc  { const float* p[4]; };
struct OPtr4 { float* o[4]; };

// ---- tf32 helpers ---------------------------------------------------------
__device__ __forceinline__ unsigned f2tf(float x) {
    unsigned r; asm("cvt.rna.tf32.f32 %0, %1;" : "=r"(r) : "f"(x)); return r;
}
__device__ __forceinline__ void mma8(float4& c,
    unsigned a0, unsigned a1, unsigned a2, unsigned a3,
    unsigned b0, unsigned b1)
{
    asm("mma.sync.aligned.m16n8k8.row.col.f32.tf32.tf32.f32 "
        "{%0,%1,%2,%3}, {%4,%5,%6,%7}, {%8,%9}, {%0,%1,%2,%3};"
        : "+f"(c.x), "+f"(c.y), "+f"(c.z), "+f"(c.w)
        : "r"(a0), "r"(a1), "r"(a2), "r"(a3), "r"(b0), "r"(b1));
}

template<int NSUM>
__device__ __forceinline__ float4 ld4sum(const ASrc& A, size_t idx) {
    float4 r = *(const float4*)(A.p[0] + idx);
    #pragma unroll
    for (int u = 1; u < NSUM; u++) {
        float4 t = *(const float4*)(A.p[u] + idx);
        r.x += t.x; r.y += t.y; r.z += t.z; r.w += t.w;
    }
    return r;
}

// ---------------------------------------------------------------------------
// NT GEMM (tf32 MMA), 128x128 tile, BK=16 single buffer w/ reg prefetch.
// C = scale * ((sum_u A_u) @ B^T + bias).  K = 1024.
// ---------------------------------------------------------------------------
template<int NSUM>
__global__ __launch_bounds__(256) void proj_tf32(ASrc Asrc, Proj3 args)
{
    const int z = blockIdx.z;
    const float* __restrict__ B    = args.W[z];
    const float* __restrict__ bias = args.bias[z];
    float* __restrict__ C          = args.C[z];
    const float scale              = args.scale[z];

    __shared__ unsigned As[16][136];
    __shared__ unsigned Bs[16][136];
    const int tid = threadIdx.x;
    const int w = tid >> 5, lane = tid & 31, g = lane >> 2, t4 = lane & 3;
    const int wm = (w >> 1) * 32, wn = (w & 1) * 64;
    const int m0 = blockIdx.y * 128, n0 = blockIdx.x * 128;
    const int lr = tid >> 1, lc = (tid & 1) * 8;
    const size_t aoff = (size_t)(m0 + lr) * DM + lc;
    const float* Bp = B + (size_t)(n0 + lr) * DM + lc;

    float4 acc[2][8];
    #pragma unroll
    for (int i = 0; i < 2; i++)
        #pragma unroll
        for (int j = 0; j < 8; j++) acc[i][j] = make_float4(0,0,0,0);

    float4 ra0 = ld4sum<NSUM>(Asrc, aoff);
    float4 ra1 = ld4sum<NSUM>(Asrc, aoff + 4);
    float4 rb0 = *(const float4*)Bp;
    float4 rb1 = *(const float4*)(Bp + 4);

    for (int k0 = 0; k0 < DM; k0 += 16) {
        __syncthreads();
        As[lc+0][lr]=f2tf(ra0.x); As[lc+1][lr]=f2tf(ra0.y);
        As[lc+2][lr]=f2tf(ra0.z); As[lc+3][lr]=f2tf(ra0.w);
        As[lc+4][lr]=f2tf(ra1.x); As[lc+5][lr]=f2tf(ra1.y);
        As[lc+6][lr]=f2tf(ra1.z); As[lc+7][lr]=f2tf(ra1.w);
        Bs[lc+0][lr]=f2tf(rb0.x); Bs[lc+1][lr]=f2tf(rb0.y);
        Bs[lc+2][lr]=f2tf(rb0.z); Bs[lc+3][lr]=f2tf(rb0.w);
        Bs[lc+4][lr]=f2tf(rb1.x); Bs[lc+5][lr]=f2tf(rb1.y);
        Bs[lc+6][lr]=f2tf(rb1.z); Bs[lc+7][lr]=f2tf(rb1.w);
        __syncthreads();
        if (k0 + 16 < DM) {
            int k = k0 + 16;
            ra0 = ld4sum<NSUM>(Asrc, aoff + k);
            ra1 = ld4sum<NSUM>(Asrc, aoff + k + 4);
            rb0 = *(const float4*)(Bp + k);
            rb1 = *(const float4*)(Bp + k + 4);
        }
        #pragma unroll
        for (int kc = 0; kc < 16; kc += 8) {
            unsigned bf[8][2];
            #pragma unroll
            for (int j = 0; j < 8; j++) {
                int cn = wn + j*8 + g;
                bf[j][0] = Bs[kc+t4][cn];
                bf[j][1] = Bs[kc+t4+4][cn];
            }
            #pragma unroll
            for (int i = 0; i < 2; i++) {
                int rm = wm + i*16 + g;
                unsigned a0 = As[kc+t4][rm],   a1 = As[kc+t4][rm+8];
                unsigned a2 = As[kc+t4+4][rm], a3 = As[kc+t4+4][rm+8];
                #pragma unroll
                for (int j = 0; j < 8; j++)
                    mma8(acc[i][j], a0, a1, a2, a3, bf[j][0], bf[j][1]);
            }
        }
    }

    #pragma unroll
    for (int i = 0; i < 2; i++) {
        int mb = m0 + wm + i*16;
        #pragma unroll
        for (int j = 0; j < 8; j++) {
            int n = n0 + wn + j*8 + t4*2;
            float2 bb = *(const float2*)(bias + n);
            float2 o0 = make_float2(scale*(acc[i][j].x + bb.x), scale*(acc[i][j].y + bb.y));
            float2 o1 = make_float2(scale*(acc[i][j].z + bb.x), scale*(acc[i][j].w + bb.y));
            *(float2*)(C + (size_t)(mb + g)     * DM + n) = o0;
            *(float2*)(C + (size_t)(mb + g + 8) * DM + n) = o1;
        }
    }
}

// ---------------------------------------------------------------------------
// exp-scores: attn[h,m,n] = mask ? 0 : exp(q.k); per-block row partial sums.
// attn writes are streaming (re-read only once, much later).
// ---------------------------------------------------------------------------
__global__ __launch_bounds__(256) void scores_tf32(
    const float* __restrict__ Q, const float* __restrict__ Km,
    const int* __restrict__ mask, float* __restrict__ attn,
    float* __restrict__ Spart)
{
    __shared__ unsigned As[8][136];
    __shared__ unsigned Bs[8][136];
    const int tid = threadIdx.x;
    const int w = tid >> 5, lane = tid & 31, g = lane >> 2, t4 = lane & 3;
    const int wm = (w >> 1) * 32, wn = (w & 1) * 64;
    const int h = blockIdx.z;
    const int m0 = blockIdx.y * 128, n0 = blockIdx.x * 128;
    const int lr = tid >> 1, lc = (tid & 1) * 4;
    const float* Ap = Q  + (size_t)(m0 + lr) * DM + h*DH + lc;
    const float* Bp = Km + (size_t)(n0 + lr) * DM + h*DH + lc;

    float4 acc[2][8];
    #pragma unroll
    for (int i = 0; i < 2; i++)
        #pragma unroll
        for (int j = 0; j < 8; j++) acc[i][j] = make_float4(0,0,0,0);

    float4 ra = *(const float4*)Ap;
    float4 rb = *(const float4*)Bp;

    for (int k0 = 0; k0 < DH; k0 += 8) {
        __syncthreads();
        As[lc+0][lr]=f2tf(ra.x); As[lc+1][lr]=f2tf(ra.y);
        As[lc+2][lr]=f2tf(ra.z); As[lc+3][lr]=f2tf(ra.w);
        Bs[lc+0][lr]=f2tf(rb.x); Bs[lc+1][lr]=f2tf(rb.y);
        Bs[lc+2][lr]=f2tf(rb.z); Bs[lc+3][lr]=f2tf(rb.w);
        __syncthreads();
        if (k0 + 8 < DH) {
            ra = *(const float4*)(Ap + k0 + 8);
            rb = *(const float4*)(Bp + k0 + 8);
        }
        unsigned bf[8][2];
        #pragma unroll
        for (int j = 0; j < 8; j++) {
            int cn = wn + j*8 + g;
            bf[j][0] = Bs[t4][cn];
            bf[j][1] = Bs[t4+4][cn];
        }
        #pragma unroll
        for (int i = 0; i < 2; i++) {
            int rm = wm + i*16 + g;
            unsigned a0 = As[t4][rm],   a1 = As[t4][rm+8];
            unsigned a2 = As[t4+4][rm], a3 = As[t4+4][rm+8];
            #pragma unroll
            for (int j = 0; j < 8; j++)
                mma8(acc[i][j], a0, a1, a2, a3, bf[j][0], bf[j][1]);
        }
    }

    float* out = attn + (size_t)h * SQ * SQ;
    #pragma unroll
    for (int i = 0; i < 2; i++) {
        int mb = m0 + wm + i*16;
        int r0 = mb + g, r1 = mb + g + 8;
        float s0 = 0.f, s1 = 0.f;
        #pragma unroll
        for (int j = 0; j < 8; j++) {
            int n = n0 + wn + j*8 + t4*2;
            int2 mv0 = *(const int2*)(mask + (size_t)r0 * SQ + n);
            int2 mv1 = *(const int2*)(mask + (size_t)r1 * SQ + n);
            float2 o0 = make_float2(mv0.x ? 0.f : __expf(acc[i][j].x),
                                    mv0.y ? 0.f : __expf(acc[i][j].y));
            float2 o1 = make_float2(mv1.x ? 0.f : __expf(acc[i][j].z),
                                    mv1.y ? 0.f : __expf(acc[i][j].w));
            s0 += o0.x + o0.y;
            s1 += o1.x + o1.y;
            __stcs((float2*)(out + (size_t)r0 * SQ + n), o0);
            __stcs((float2*)(out + (size_t)r1 * SQ + n), o1);
        }
        s0 += __shfl_xor_sync(0xffffffffu, s0, 1);
        s0 += __shfl_xor_sync(0xffffffffu, s0, 2);
        s1 += __shfl_xor_sync(0xffffffffu, s1, 1);
        s1 += __shfl_xor_sync(0xffffffffu, s1, 2);
        if (t4 == 0) {
            int slot = blockIdx.x * 2 + (wn ? 1 : 0);
            Spart[(size_t)((h << 11) + r0) * 32 + slot] = s0;
            Spart[(size_t)((h << 11) + r1) * 32 + slot] = s1;
        }
    }
}

// ---------------------------------------------------------------------------
__global__ __launch_bounds__(256) void sum_rows(
    const float* __restrict__ Spart, float* __restrict__ S)
{
    int r = blockIdx.x * 256 + threadIdx.x;
    const float4* p = (const float4*)(Spart + (size_t)r * 32);
    float s = 0.f;
    #pragma unroll
    for (int u = 0; u < 8; u++) {
        float4 v = p[u];
        s += (v.x + v.y) + (v.z + v.w);
    }
    S[r] = s;
}

// ---------------------------------------------------------------------------
// av partial (tf32 MMA, NN): K-split 4.  MMA on raw exp; ctx scaled by invS
// in epilogue; normalized attn written back via streaming stores.
// 128x64 tile, BK=16 ping-pong, 256 threads. grid (16,16,4) = 1024 blocks.
// ---------------------------------------------------------------------------
#define KSPLIT 4
__global__ __launch_bounds__(256) void av_tf32(
    float* __restrict__ attn, const float* __restrict__ V,
    const float* __restrict__ S, OPtr4 parts)
{
    __shared__ unsigned Ps[2][16][136];
    __shared__ unsigned Vs[2][16][72];
    const int tid = threadIdx.x;
    const int w = tid >> 5, lane = tid & 31, g = lane >> 2, t4 = lane & 3;
    const int wm = (w >> 1) * 32, wn = (w & 1) * 32;
    const int h = blockIdx.y;
    const int m0 = blockIdx.x * 128;
    const int kb = blockIdx.z * (SQ / KSPLIT);
    float* ctx = parts.o[blockIdx.z];
    const float* Vb = V + (size_t)kb * DM + h * DH;

    const int pr = tid >> 1;
    const int pc = (tid & 1) * 8;
    const int vr = tid >> 4;
    const int vc = (tid & 15) * 4;

    const float invS = 1.0f / S[(h << 11) + m0 + pr];
    float* Prow = attn + (size_t)h * SQ * SQ + (size_t)(m0 + pr) * SQ + kb;

    float4 acc[2][4];
    #pragma unroll
    for (int i = 0; i < 2; i++)
        #pragma unroll
        for (int j = 0; j < 4; j++) acc[i][j] = make_float4(0,0,0,0);

    const int NS = (SQ/KSPLIT) / 16;   // 32 stages

    {
        float4 rp0 = __ldcs((const float4*)(Prow + pc));
        float4 rp1 = __ldcs((const float4*)(Prow + pc + 4));
        float4 rv  = *(const float4*)(Vb + (size_t)vr * DM + vc);
        Ps[0][pc+0][pr]=f2tf(rp0.x); Ps[0][pc+1][pr]=f2tf(rp0.y);
        Ps[0][pc+2][pr]=f2tf(rp0.z); Ps[0][pc+3][pr]=f2tf(rp0.w);
        Ps[0][pc+4][pr]=f2tf(rp1.x); Ps[0][pc+5][pr]=f2tf(rp1.y);
        Ps[0][pc+6][pr]=f2tf(rp1.z); Ps[0][pc+7][pr]=f2tf(rp1.w);
        Vs[0][vr][vc+0]=f2tf(rv.x); Vs[0][vr][vc+1]=f2tf(rv.y);
        Vs[0][vr][vc+2]=f2tf(rv.z); Vs[0][vr][vc+3]=f2tf(rv.w);
        float4 w0 = make_float4(rp0.x*invS, rp0.y*invS, rp0.z*invS, rp0.w*invS);
        float4 w1 = make_float4(rp1.x*invS, rp1.y*invS, rp1.z*invS, rp1.w*invS);
        __stcs((float4*)(Prow + pc), w0);
        __stcs((float4*)(Prow + pc + 4), w1);
    }
    float4 qp0 = __ldcs((const float4*)(Prow + 16 + pc));
    float4 qp1 = __ldcs((const float4*)(Prow + 16 + pc + 4));
    float4 qv  = *(const float4*)(Vb + (size_t)(16 + vr) * DM + vc);
    __syncthreads();

    for (int s = 0; s < NS; s++) {
        const int cur = s & 1;
        if (s + 1 < NS) {
            unsigned (*Pd)[136] = Ps[cur ^ 1];
            unsigned (*Vd)[72]  = Vs[cur ^ 1];
            Pd[pc+0][pr]=f2tf(qp0.x); Pd[pc+1][pr]=f2tf(qp0.y);
            Pd[pc+2][pr]=f2tf(qp0.z); Pd[pc+3][pr]=f2tf(qp0.w);
            Pd[pc+4][pr]=f2tf(qp1.x); Pd[pc+5][pr]=f2tf(qp1.y);
            Pd[pc+6][pr]=f2tf(qp1.z); Pd[pc+7][pr]=f2tf(qp1.w);
            Vd[vr][vc+0]=f2tf(qv.x); Vd[vr][vc+1]=f2tf(qv.y);
            Vd[vr][vc+2]=f2tf(qv.z); Vd[vr][vc+3]=f2tf(qv.w);
            float4 w0 = make_float4(qp0.x*invS, qp0.y*invS, qp0.z*invS, qp0.w*invS);
            float4 w1 = make_float4(qp1.x*invS, qp1.y*invS, qp1.z*invS, qp1.w*invS);
            __stcs((float4*)(Prow + (s+1)*16 + pc), w0);
            __stcs((float4*)(Prow + (s+1)*16 + pc + 4), w1);
        }
        if (s + 2 < NS) {
            int k = (s + 2) * 16;
            qp0 = __ldcs((const float4*)(Prow + k + pc));
            qp1 = __ldcs((const float4*)(Prow + k + pc + 4));
            qv  = *(const float4*)(Vb + (size_t)(k + vr) * DM + vc);
        }
        unsigned (*Pc)[136] = Ps[cur];
        unsigned (*Vc)[72]  = Vs[cur];
        #pragma unroll
        for (int ks = 0; ks < 16; ks += 8) {
            unsigned bf[4][2];
            #pragma unroll
            for (int j = 0; j < 4; j++) {
                int cn = wn + j*8 + g;
                bf[j][0] = Vc[ks + t4][cn];
                bf[j][1] = Vc[ks + t4 + 4][cn];
            }
            #pragma unroll
            for (int i = 0; i < 2; i++) {
                int rm = wm + i*16 + g;
                unsigned a0 = Pc[ks+t4][rm],   a1 = Pc[ks+t4][rm+8];
                unsigned a2 = Pc[ks+t4+4][rm], a3 = Pc[ks+t4+4][rm+8];
                #pragma unroll
                for (int j = 0; j < 4; j++)
                    mma8(acc[i][j], a0, a1, a2, a3, bf[j][0], bf[j][1]);
            }
        }
        __syncthreads();
    }

    #pragma unroll
    for (int i = 0; i < 2; i++) {
        int mb = m0 + wm + i*16;
        float is0 = 1.0f / S[(h << 11) + mb + g];
        float is1 = 1.0f / S[(h << 11) + mb + g + 8];
        #pragma unroll
        for (int j = 0; j < 4; j++) {
            int n = h*DH + wn + j*8 + t4*2;
            *(float2*)(ctx + (size_t)(mb + g)     * DM + n) = make_float2(acc[i][j].x*is0, acc[i][j].y*is0);
            *(float2*)(ctx + (size_t)(mb + g + 8) * DM + n) = make_float2(acc[i][j].z*is1, acc[i][j].w*is1);
        }
    }
}

// ---------------------------------------------------------------------------
extern "C" void kernel_launch(void* const* d_in, const int* in_sizes, int n_in,
                              void* d_out, int out_size)
{
    const float* X    = (const float*)d_in[0];
    const int*   mask = (const int*)d_in[1];
    const float* Wq   = (const float*)d_in[2];
    const float* bq   = (const float*)d_in[3];
    const float* Wk   = (const float*)d_in[4];
    const float* bk   = (const float*)d_in[5];
    const float* Wv   = (const float*)d_in[6];
    const float* bv   = (const float*)d_in[7];
    const float* Wo   = (const float*)d_in[8];
    const float* bo   = (const float*)d_in[9];

    float* out  = (float*)d_out;                 // (S, D)
    float* attn = out + (size_t)SQ * DM;         // (H, S, S)

    float *Qb, *Kb, *Vb, *Cb, *P3, *Sp, *Sb;
    cudaGetSymbolAddress((void**)&Qb, g_Q);
    cudaGetSymbolAddress((void**)&Kb, g_K);
    cudaGetSymbolAddress((void**)&Vb, g_V);
    cudaGetSymbolAddress((void**)&Cb, g_C);
    cudaGetSymbolAddress((void**)&P3, g_P3);
    cudaGetSymbolAddress((void**)&Sp, g_Spart);
    cudaGetSymbolAddress((void**)&Sb, g_S);

    // QKV projections fused into one launch (scale 1/8 folded into Q)
    Proj3 pa;
    pa.W[0]=Wq; pa.W[1]=Wk; pa.W[2]=Wv;
    pa.bias[0]=bq; pa.bias[1]=bk; pa.bias[2]=bv;
    pa.C[0]=Qb; pa.C[1]=Kb; pa.C[2]=Vb;
    pa.scale[0]=0.125f; pa.scale[1]=1.0f; pa.scale[2]=1.0f;
    ASrc ax; ax.p[0]=X; ax.p[1]=nullptr; ax.p[2]=nullptr; ax.p[3]=nullptr;
    proj_tf32<1><<<dim3(8, 16, 3), 256>>>(ax, pa);

    // exp(scores) + partial row sums
    scores_tf32<<<dim3(16, 16, 16), 256>>>(Qb, Kb, mask, attn, Sp);
    sum_rows<<<NH * SQ / 256, 256>>>(Sp, Sb);

    // av K-split-4: partials into g_C, g_Q, g_K (both dead), g_P3
    OPtr4 op; op.o[0]=Cb; op.o[1]=Qb; op.o[2]=Kb; op.o[3]=P3;
    av_tf32<<<dim3(16, 16, KSPLIT), 256>>>(attn, Vb, Sb, op);

    // out = (p0+p1+p2+p3) @ Wo^T + bo  (reduction fused into A loads)
    Proj3 po;
    po.W[0]=Wo; po.bias[0]=bo; po.C[0]=out; po.scale[0]=1.0f;
    po.W[1]=Wo; po.bias[1]=bo; po.C[1]=out; po.scale[1]=1.0f;
    po.W[2]=Wo; po.bias[2]=bo; po.C[2]=out; po.scale[2]=1.0f;
    ASrc ac; ac.p[0]=Cb; ac.p[1]=Qb; ac.p[2]=Kb; ac.p[3]=P3;
    proj_tf32<4><<<dim3(8, 16, 1), 256>>>(ac, po);
}

// round 15
// speedup vs baseline: 1.0018x; 1.0018x over previous
#include <cuda_runtime.h>

#define SQ 2048
#define DM 1024
#define NH 16
#define DH 64

// Scratch (device globals; no allocation allowed)
__device__ float g_Q[SQ * DM];   // Q; later av partial #1
__device__ float g_K[SQ * DM];   // K; later av partial #2
__device__ float g_V[SQ * DM];
__device__ float g_C[SQ * DM];   // av partial #0
__device__ float g_P3[SQ * DM];  // av partial #3
__device__ float g_Spart[NH * SQ * 32];
__device__ float g_S[NH * SQ];

struct Proj3 {
    const float* W[3];
    const float* bias[3];
    float* C[3];
    float scale[3];
};
struct ASrc  { const float* p[4]; };
struct OPtr4 { float* o[4]; };

// ---- tf32 helpers ---------------------------------------------------------
__device__ __forceinline__ unsigned f2tf(float x) {
    unsigned r; asm("cvt.rna.tf32.f32 %0, %1;" : "=r"(r) : "f"(x)); return r;
}
__device__ __forceinline__ uint4 f2tf4(float4 v) {
    uint4 r; r.x=f2tf(v.x); r.y=f2tf(v.y); r.z=f2tf(v.z); r.w=f2tf(v.w); return r;
}
__device__ __forceinline__ void mma8(float4& c,
    unsigned a0, unsigned a1, unsigned a2, unsigned a3,
    unsigned b0, unsigned b1)
{
    asm("mma.sync.aligned.m16n8k8.row.col.f32.tf32.tf32.f32 "
        "{%0,%1,%2,%3}, {%4,%5,%6,%7}, {%8,%9}, {%0,%1,%2,%3};"
        : "+f"(c.x), "+f"(c.y), "+f"(c.z), "+f"(c.w)
        : "r"(a0), "r"(a1), "r"(a2), "r"(a3), "r"(b0), "r"(b1));
}

template<int NSUM>
__device__ __forceinline__ float4 ld4sum(const ASrc& A, size_t idx) {
    float4 r = *(const float4*)(A.p[0] + idx);
    #pragma unroll
    for (int u = 1; u < NSUM; u++) {
        float4 t = *(const float4*)(A.p[u] + idx);
        r.x += t.x; r.y += t.y; r.z += t.z; r.w += t.w;
    }
    return r;
}

// ---------------------------------------------------------------------------
// NT GEMM (tf32 MMA), 128x128 tile, BK=16, row-major smem [row][20].
// C = scale * ((sum_u A_u) @ B^T + bias).  K = 1024.
// ---------------------------------------------------------------------------
template<int NSUM>
__global__ __launch_bounds__(256) void proj_tf32(ASrc Asrc, Proj3 args)
{
    const int z = blockIdx.z;
    const float* __restrict__ B    = args.W[z];
    const float* __restrict__ bias = args.bias[z];
    float* __restrict__ C          = args.C[z];
    const float scale              = args.scale[z];

    __shared__ unsigned As[128][20];   // [m][k], stride 20: conflict-free frags
    __shared__ unsigned Bs[128][20];   // [n][k]
    const int tid = threadIdx.x;
    const int w = tid >> 5, lane = tid & 31, g = lane >> 2, t4 = lane & 3;
    const int wm = (w >> 1) * 32, wn = (w & 1) * 64;
    const int m0 = blockIdx.y * 128, n0 = blockIdx.x * 128;
    const int lr = tid >> 1, lc = (tid & 1) * 8;
    const size_t aoff = (size_t)(m0 + lr) * DM + lc;
    const float* Bp = B + (size_t)(n0 + lr) * DM + lc;

    float4 acc[2][8];
    #pragma unroll
    for (int i = 0; i < 2; i++)
        #pragma unroll
        for (int j = 0; j < 8; j++) acc[i][j] = make_float4(0,0,0,0);

    float4 ra0 = ld4sum<NSUM>(Asrc, aoff);
    float4 ra1 = ld4sum<NSUM>(Asrc, aoff + 4);
    float4 rb0 = *(const float4*)Bp;
    float4 rb1 = *(const float4*)(Bp + 4);

    for (int k0 = 0; k0 < DM; k0 += 16) {
        __syncthreads();
        *(uint4*)&As[lr][lc]     = f2tf4(ra0);
        *(uint4*)&As[lr][lc + 4] = f2tf4(ra1);
        *(uint4*)&Bs[lr][lc]     = f2tf4(rb0);
        *(uint4*)&Bs[lr][lc + 4] = f2tf4(rb1);
        __syncthreads();
        if (k0 + 16 < DM) {
            int k = k0 + 16;
            ra0 = ld4sum<NSUM>(Asrc, aoff + k);
            ra1 = ld4sum<NSUM>(Asrc, aoff + k + 4);
            rb0 = *(const float4*)(Bp + k);
            rb1 = *(const float4*)(Bp + k + 4);
        }
        #pragma unroll
        for (int kc = 0; kc < 16; kc += 8) {
            unsigned bf[8][2];
            #pragma unroll
            for (int j = 0; j < 8; j++) {
                int cn = wn + j*8 + g;
                bf[j][0] = Bs[cn][kc + t4];
                bf[j][1] = Bs[cn][kc + t4 + 4];
            }
            #pragma unroll
            for (int i = 0; i < 2; i++) {
                int rm = wm + i*16 + g;
                unsigned a0 = As[rm][kc+t4],   a1 = As[rm+8][kc+t4];
                unsigned a2 = As[rm][kc+t4+4], a3 = As[rm+8][kc+t4+4];
                #pragma unroll
                for (int j = 0; j < 8; j++)
                    mma8(acc[i][j], a0, a1, a2, a3, bf[j][0], bf[j][1]);
            }
        }
    }

    #pragma unroll
    for (int i = 0; i < 2; i++) {
        int mb = m0 + wm + i*16;
        #pragma unroll
        for (int j = 0; j < 8; j++) {
            int n = n0 + wn + j*8 + t4*2;
            float2 bb = *(const float2*)(bias + n);
            float2 o0 = make_float2(scale*(acc[i][j].x + bb.x), scale*(acc[i][j].y + bb.y));
            float2 o1 = make_float2(scale*(acc[i][j].z + bb.x), scale*(acc[i][j].w + bb.y));
            *(float2*)(C + (size_t)(mb + g)     * DM + n) = o0;
            *(float2*)(C + (size_t)(mb + g + 8) * DM + n) = o1;
        }
    }
}

// ---------------------------------------------------------------------------
// exp-scores: attn[h,m,n] = mask ? 0 : exp(q.k); per-block row partial sums.
// Row-major smem [row][12] (8 k + pad 4), vectorized STS.
// ---------------------------------------------------------------------------
__global__ __launch_bounds__(256) void scores_tf32(
    const float* __restrict__ Q, const float* __restrict__ Km,
    const int* __restrict__ mask, float* __restrict__ attn,
    float* __restrict__ Spart)
{
    __shared__ unsigned As[128][12];
    __shared__ unsigned Bs[128][12];
    const int tid = threadIdx.x;
    const int w = tid >> 5, lane = tid & 31, g = lane >> 2, t4 = lane & 3;
    const int wm = (w >> 1) * 32, wn = (w & 1) * 64;
    const int h = blockIdx.z;
    const int m0 = blockIdx.y * 128, n0 = blockIdx.x * 128;
    const int lr = tid >> 1, lc = (tid & 1) * 4;
    const float* Ap = Q  + (size_t)(m0 + lr) * DM + h*DH + lc;
    const float* Bp = Km + (size_t)(n0 + lr) * DM + h*DH + lc;

    float4 acc[2][8];
    #pragma unroll
    for (int i = 0; i < 2; i++)
        #pragma unroll
        for (int j = 0; j < 8; j++) acc[i][j] = make_float4(0,0,0,0);

    float4 ra = *(const float4*)Ap;
    float4 rb = *(const float4*)Bp;

    for (int k0 = 0; k0 < DH; k0 += 8) {
        __syncthreads();
        *(uint4*)&As[lr][lc] = f2tf4(ra);
        *(uint4*)&Bs[lr][lc] = f2tf4(rb);
        __syncthreads();
        if (k0 + 8 < DH) {
            ra = *(const float4*)(Ap + k0 + 8);
            rb = *(const float4*)(Bp + k0 + 8);
        }
        unsigned bf[8][2];
        #pragma unroll
        for (int j = 0; j < 8; j++) {
            int cn = wn + j*8 + g;
            bf[j][0] = Bs[cn][t4];
            bf[j][1] = Bs[cn][t4 + 4];
        }
        #pragma unroll
        for (int i = 0; i < 2; i++) {
            int rm = wm + i*16 + g;
            unsigned a0 = As[rm][t4],   a1 = As[rm+8][t4];
            unsigned a2 = As[rm][t4+4], a3 = As[rm+8][t4+4];
            #pragma unroll
            for (int j = 0; j < 8; j++)
                mma8(acc[i][j], a0, a1, a2, a3, bf[j][0], bf[j][1]);
        }
    }

    float* out = attn + (size_t)h * SQ * SQ;
    #pragma unroll
    for (int i = 0; i < 2; i++) {
        int mb = m0 + wm + i*16;
        int r0 = mb + g, r1 = mb + g + 8;
        float s0 = 0.f, s1 = 0.f;
        #pragma unroll
        for (int j = 0; j < 8; j++) {
            int n = n0 + wn + j*8 + t4*2;
            int2 mv0 = *(const int2*)(mask + (size_t)r0 * SQ + n);
            int2 mv1 = *(const int2*)(mask + (size_t)r1 * SQ + n);
            float2 o0 = make_float2(mv0.x ? 0.f : __expf(acc[i][j].x),
                                    mv0.y ? 0.f : __expf(acc[i][j].y));
            float2 o1 = make_float2(mv1.x ? 0.f : __expf(acc[i][j].z),
                                    mv1.y ? 0.f : __expf(acc[i][j].w));
            s0 += o0.x + o0.y;
            s1 += o1.x + o1.y;
            *(float2*)(out + (size_t)r0 * SQ + n) = o0;
            *(float2*)(out + (size_t)r1 * SQ + n) = o1;
        }
        s0 += __shfl_xor_sync(0xffffffffu, s0, 1);
        s0 += __shfl_xor_sync(0xffffffffu, s0, 2);
        s1 += __shfl_xor_sync(0xffffffffu, s1, 1);
        s1 += __shfl_xor_sync(0xffffffffu, s1, 2);
        if (t4 == 0) {
            int slot = blockIdx.x * 2 + (wn ? 1 : 0);
            Spart[(size_t)((h << 11) + r0) * 32 + slot] = s0;
            Spart[(size_t)((h << 11) + r1) * 32 + slot] = s1;
        }
    }
}

// ---------------------------------------------------------------------------
__global__ __launch_bounds__(256) void sum_rows(
    const float* __restrict__ Spart, float* __restrict__ S)
{
    int r = blockIdx.x * 256 + threadIdx.x;
    const float4* p = (const float4*)(Spart + (size_t)r * 32);
    float s = 0.f;
    #pragma unroll
    for (int u = 0; u < 8; u++) {
        float4 v = p[u];
        s += (v.x + v.y) + (v.z + v.w);
    }
    S[r] = s;
}

// ---------------------------------------------------------------------------
// av partial (tf32 MMA, NN): K-split 4.  P staged row-major [m][20] with
// vectorized STS; MMA on raw exp; ctx scaled by invS in epilogue; normalized
// attn written back via streaming stores.  128x64 tile, BK=16 ping-pong.
// ---------------------------------------------------------------------------
#define KSPLIT 4
__global__ __launch_bounds__(256) void av_tf32(
    float* __restrict__ attn, const float* __restrict__ V,
    const float* __restrict__ S, OPtr4 parts)
{
    __shared__ unsigned Ps[2][128][20];  // [buf][m][k]
    __shared__ unsigned Vs[2][16][72];   // [buf][k][n]
    const int tid = threadIdx.x;
    const int w = tid >> 5, lane = tid & 31, g = lane >> 2, t4 = lane & 3;
    const int wm = (w >> 1) * 32, wn = (w & 1) * 32;
    const int h = blockIdx.y;
    const int m0 = blockIdx.x * 128;
    const int kb = blockIdx.z * (SQ / KSPLIT);
    float* ctx = parts.o[blockIdx.z];
    const float* Vb = V + (size_t)kb * DM + h * DH;

    const int pr = tid >> 1;
    const int pc = (tid & 1) * 8;
    const int vr = tid >> 4;
    const int vc = (tid & 15) * 4;

    const float invS = 1.0f / S[(h << 11) + m0 + pr];
    float* Prow = attn + (size_t)h * SQ * SQ + (size_t)(m0 + pr) * SQ + kb;

    float4 acc[2][4];
    #pragma unroll
    for (int i = 0; i < 2; i++)
        #pragma unroll
        for (int j = 0; j < 4; j++) acc[i][j] = make_float4(0,0,0,0);

    const int NS = (SQ/KSPLIT) / 16;   // 32 stages

    {
        float4 rp0 = __ldcs((const float4*)(Prow + pc));
        float4 rp1 = __ldcs((const float4*)(Prow + pc + 4));
        float4 rv  = *(const float4*)(Vb + (size_t)vr * DM + vc);
        *(uint4*)&Ps[0][pr][pc]     = f2tf4(rp0);
        *(uint4*)&Ps[0][pr][pc + 4] = f2tf4(rp1);
        *(uint4*)&Vs[0][vr][vc]     = f2tf4(rv);
        float4 w0 = make_float4(rp0.x*invS, rp0.y*invS, rp0.z*invS, rp0.w*invS);
        float4 w1 = make_float4(rp1.x*invS, rp1.y*invS, rp1.z*invS, rp1.w*invS);
        __stcs((float4*)(Prow + pc), w0);
        __stcs((float4*)(Prow + pc + 4), w1);
    }
    float4 qp0 = __ldcs((const float4*)(Prow + 16 + pc));
    float4 qp1 = __ldcs((const float4*)(Prow + 16 + pc + 4));
    float4 qv  = *(const float4*)(Vb + (size_t)(16 + vr) * DM + vc);
    __syncthreads();

    for (int s = 0; s < NS; s++) {
        const int cur = s & 1;
        if (s + 1 < NS) {
            *(uint4*)&Ps[cur ^ 1][pr][pc]     = f2tf4(qp0);
            *(uint4*)&Ps[cur ^ 1][pr][pc + 4] = f2tf4(qp1);
            *(uint4*)&Vs[cur ^ 1][vr][vc]     = f2tf4(qv);
            float4 w0 = make_float4(qp0.x*invS, qp0.y*invS, qp0.z*invS, qp0.w*invS);
            float4 w1 = make_float4(qp1.x*invS, qp1.y*invS, qp1.z*invS, qp1.w*invS);
            __stcs((float4*)(Prow + (s+1)*16 + pc), w0);
            __stcs((float4*)(Prow + (s+1)*16 + pc + 4), w1);
        }
        if (s + 2 < NS) {
            int k = (s + 2) * 16;
            qp0 = __ldcs((const float4*)(Prow + k + pc));
            qp1 = __ldcs((const float4*)(Prow + k + pc + 4));
            qv  = *(const float4*)(Vb + (size_t)(k + vr) * DM + vc);
        }
        unsigned (*Pc)[20] = Ps[cur];
        unsigned (*Vc)[72] = Vs[cur];
        #pragma unroll
        for (int ks = 0; ks < 16; ks += 8) {
            unsigned bf[4][2];
            #pragma unroll
            for (int j = 0; j < 4; j++) {
                int cn = wn + j*8 + g;
                bf[j][0] = Vc[ks + t4][cn];
                bf[j][1] = Vc[ks + t4 + 4][cn];
            }
            #pragma unroll
            for (int i = 0; i < 2; i++) {
                int rm = wm + i*16 + g;
                unsigned a0 = Pc[rm][ks+t4],   a1 = Pc[rm+8][ks+t4];
                unsigned a2 = Pc[rm][ks+t4+4], a3 = Pc[rm+8][ks+t4+4];
                #pragma unroll
                for (int j = 0; j < 4; j++)
                    mma8(acc[i][j], a0, a1, a2, a3, bf[j][0], bf[j][1]);
            }
        }
        __syncthreads();
    }

    #pragma unroll
    for (int i = 0; i < 2; i++) {
        int mb = m0 + wm + i*16;
        float is0 = 1.0f / S[(h << 11) + mb + g];
        float is1 = 1.0f / S[(h << 11) + mb + g + 8];
        #pragma unroll
        for (int j = 0; j < 4; j++) {
            int n = h*DH + wn + j*8 + t4*2;
            *(float2*)(ctx + (size_t)(mb + g)     * DM + n) = make_float2(acc[i][j].x*is0, acc[i][j].y*is0);
            *(float2*)(ctx + (size_t)(mb + g + 8) * DM + n) = make_float2(acc[i][j].z*is1, acc[i][j].w*is1);
        }
    }
}

// ---------------------------------------------------------------------------
extern "C" void kernel_launch(void* const* d_in, const int* in_sizes, int n_in,
                              void* d_out, int out_size)
{
    const float* X    = (const float*)d_in[0];
    const int*   mask = (const int*)d_in[1];
    const float* Wq   = (const float*)d_in[2];
    const float* bq   = (const float*)d_in[3];
    const float* Wk   = (const float*)d_in[4];
    const float* bk   = (const float*)d_in[5];
    const float* Wv   = (const float*)d_in[6];
    const float* bv   = (const float*)d_in[7];
    const float* Wo   = (const float*)d_in[8];
    const float* bo   = (const float*)d_in[9];

    float* out  = (float*)d_out;                 // (S, D)
    float* attn = out + (size_t)SQ * DM;         // (H, S, S)

    float *Qb, *Kb, *Vb, *Cb, *P3, *Sp, *Sb;
    cudaGetSymbolAddress((void**)&Qb, g_Q);
    cudaGetSymbolAddress((void**)&Kb, g_K);
    cudaGetSymbolAddress((void**)&Vb, g_V);
    cudaGetSymbolAddress((void**)&Cb, g_C);
    cudaGetSymbolAddress((void**)&P3, g_P3);
    cudaGetSymbolAddress((void**)&Sp, g_Spart);
    cudaGetSymbolAddress((void**)&Sb, g_S);

    // QKV projections fused into one launch (scale 1/8 folded into Q)
    Proj3 pa;
    pa.W[0]=Wq; pa.W[1]=Wk; pa.W[2]=Wv;
    pa.bias[0]=bq; pa.bias[1]=bk; pa.bias[2]=bv;
    pa.C[0]=Qb; pa.C[1]=Kb; pa.C[2]=Vb;
    pa.scale[0]=0.125f; pa.scale[1]=1.0f; pa.scale[2]=1.0f;
    ASrc ax; ax.p[0]=X; ax.p[1]=nullptr; ax.p[2]=nullptr; ax.p[3]=nullptr;
    proj_tf32<1><<<dim3(8, 16, 3), 256>>>(ax, pa);

    // exp(scores) + partial row sums
    scores_tf32<<<dim3(16, 16, 16), 256>>>(Qb, Kb, mask, attn, Sp);
    sum_rows<<<NH * SQ / 256, 256>>>(Sp, Sb);

    // av K-split-4: partials into g_C, g_Q, g_K (both dead), g_P3
    OPtr4 op; op.o[0]=Cb; op.o[1]=Qb; op.o[2]=Kb; op.o[3]=P3;
    av_tf32<<<dim3(16, 16, KSPLIT), 256>>>(attn, Vb, Sb, op);

    // out = (p0+p1+p2+p3) @ Wo^T + bo  (reduction fused into A loads)
    Proj3 po;
    po.W[0]=Wo; po.bias[0]=bo; po.C[0]=out; po.scale[0]=1.0f;
    po.W[1]=Wo; po.bias[1]=bo; po.C[1]=out; po.scale[1]=1.0f;
    po.W[2]=Wo; po.bias[2]=bo; po.C[2]=out; po.scale[2]=1.0f;
    ASrc ac; ac.p[0]=Cb; ac.p[1]=Qb; ac.p[2]=Kb; ac.p[3]=P3;
    proj_tf32<4><<<dim3(8, 16, 1), 256>>>(ac, po);
}

// round 16
// speedup vs baseline: 1.0524x; 1.0504x over previous
#include <cuda_runtime.h>

#define SQ 2048
#define DM 1024
#define NH 16
#define DH 64

// Scratch (device globals; no allocation allowed)
__device__ float g_Q[SQ * DM];   // Q; later av partial #1
__device__ float g_K[SQ * DM];   // K; later av partial #2
__device__ float g_V[SQ * DM];
__device__ float g_C[SQ * DM];   // av partial #0
__device__ float g_P3[SQ * DM];  // av partial #3
__device__ float g_Spart[NH * SQ * 32];
__device__ float g_S[NH * SQ];

struct Proj3 {
    const float* W[3];
    const float* bias[3];
    float* C[3];
    float scale[3];
};
struct ASrc  { const float* p[4]; };
struct OPtr4 { float* o[4]; };

// ---- tf32 helpers ---------------------------------------------------------
__device__ __forceinline__ unsigned f2tf(float x) {
    unsigned r; asm("cvt.rna.tf32.f32 %0, %1;" : "=r"(r) : "f"(x)); return r;
}
__device__ __forceinline__ uint4 f2tf4(float4 v) {
    uint4 r; r.x=f2tf(v.x); r.y=f2tf(v.y); r.z=f2tf(v.z); r.w=f2tf(v.w); return r;
}
__device__ __forceinline__ void mma8(float4& c,
    unsigned a0, unsigned a1, unsigned a2, unsigned a3,
    unsigned b0, unsigned b1)
{
    asm("mma.sync.aligned.m16n8k8.row.col.f32.tf32.tf32.f32 "
        "{%0,%1,%2,%3}, {%4,%5,%6,%7}, {%8,%9}, {%0,%1,%2,%3};"
        : "+f"(c.x), "+f"(c.y), "+f"(c.z), "+f"(c.w)
        : "r"(a0), "r"(a1), "r"(a2), "r"(a3), "r"(b0), "r"(b1));
}

template<int NSUM>
__device__ __forceinline__ float4 ld4sum(const ASrc& A, size_t idx) {
    float4 r = *(const float4*)(A.p[0] + idx);
    #pragma unroll
    for (int u = 1; u < NSUM; u++) {
        float4 t = *(const float4*)(A.p[u] + idx);
        r.x += t.x; r.y += t.y; r.z += t.z; r.w += t.w;
    }
    return r;
}

// ---------------------------------------------------------------------------
// NT GEMM (tf32 MMA), 128x128 tile, BK=16, row-major smem [row][20].
// C = scale * ((sum_u A_u) @ B^T + bias).  K = 1024.
// ---------------------------------------------------------------------------
template<int NSUM>
__global__ __launch_bounds__(256) void proj_tf32(ASrc Asrc, Proj3 args)
{
    const int z = blockIdx.z;
    const float* __restrict__ B    = args.W[z];
    const float* __restrict__ bias = args.bias[z];
    float* __restrict__ C          = args.C[z];
    const float scale              = args.scale[z];

    __shared__ unsigned As[128][20];
    __shared__ unsigned Bs[128][20];
    const int tid = threadIdx.x;
    const int w = tid >> 5, lane = tid & 31, g = lane >> 2, t4 = lane & 3;
    const int wm = (w >> 1) * 32, wn = (w & 1) * 64;
    const int m0 = blockIdx.y * 128, n0 = blockIdx.x * 128;
    const int lr = tid >> 1, lc = (tid & 1) * 8;
    const size_t aoff = (size_t)(m0 + lr) * DM + lc;
    const float* Bp = B + (size_t)(n0 + lr) * DM + lc;

    float4 acc[2][8];
    #pragma unroll
    for (int i = 0; i < 2; i++)
        #pragma unroll
        for (int j = 0; j < 8; j++) acc[i][j] = make_float4(0,0,0,0);

    float4 ra0 = ld4sum<NSUM>(Asrc, aoff);
    float4 ra1 = ld4sum<NSUM>(Asrc, aoff + 4);
    float4 rb0 = *(const float4*)Bp;
    float4 rb1 = *(const float4*)(Bp + 4);

    for (int k0 = 0; k0 < DM; k0 += 16) {
        __syncthreads();
        *(uint4*)&As[lr][lc]     = f2tf4(ra0);
        *(uint4*)&As[lr][lc + 4] = f2tf4(ra1);
        *(uint4*)&Bs[lr][lc]     = f2tf4(rb0);
        *(uint4*)&Bs[lr][lc + 4] = f2tf4(rb1);
        __syncthreads();
        if (k0 + 16 < DM) {
            int k = k0 + 16;
            ra0 = ld4sum<NSUM>(Asrc, aoff + k);
            ra1 = ld4sum<NSUM>(Asrc, aoff + k + 4);
            rb0 = *(const float4*)(Bp + k);
            rb1 = *(const float4*)(Bp + k + 4);
        }
        #pragma unroll
        for (int kc = 0; kc < 16; kc += 8) {
            unsigned bf[8][2];
            #pragma unroll
            for (int j = 0; j < 8; j++) {
                int cn = wn + j*8 + g;
                bf[j][0] = Bs[cn][kc + t4];
                bf[j][1] = Bs[cn][kc + t4 + 4];
            }
            #pragma unroll
            for (int i = 0; i < 2; i++) {
                int rm = wm + i*16 + g;
                unsigned a0 = As[rm][kc+t4],   a1 = As[rm+8][kc+t4];
                unsigned a2 = As[rm][kc+t4+4], a3 = As[rm+8][kc+t4+4];
                #pragma unroll
                for (int j = 0; j < 8; j++)
                    mma8(acc[i][j], a0, a1, a2, a3, bf[j][0], bf[j][1]);
            }
        }
    }

    #pragma unroll
    for (int i = 0; i < 2; i++) {
        int mb = m0 + wm + i*16;
        #pragma unroll
        for (int j = 0; j < 8; j++) {
            int n = n0 + wn + j*8 + t4*2;
            float2 bb = *(const float2*)(bias + n);
            float2 o0 = make_float2(scale*(acc[i][j].x + bb.x), scale*(acc[i][j].y + bb.y));
            float2 o1 = make_float2(scale*(acc[i][j].z + bb.x), scale*(acc[i][j].w + bb.y));
            *(float2*)(C + (size_t)(mb + g)     * DM + n) = o0;
            *(float2*)(C + (size_t)(mb + g + 8) * DM + n) = o1;
        }
    }
}

// ---------------------------------------------------------------------------
// exp-scores v2: SINGLE-BARRIER.  Whole 128x64 Q and K tiles staged in
// dynamic smem ([128][68] tf32 each, 69.6 KB); one __syncthreads; 64 k-steps
// of MMAs barrier-free.  attn[h,m,n] = mask ? 0 : exp(q.k); per-block row
// partial sums -> Spart.
// ---------------------------------------------------------------------------
#define SC_STRIDE 68
#define SC_SMEM (2 * 128 * SC_STRIDE * 4)

__global__ __launch_bounds__(256) void scores_tf32(
    const float* __restrict__ Q, const float* __restrict__ Km,
    const int* __restrict__ mask, float* __restrict__ attn,
    float* __restrict__ Spart)
{
    extern __shared__ unsigned sc_smem[];
    unsigned (*As)[SC_STRIDE] = (unsigned (*)[SC_STRIDE])sc_smem;
    unsigned (*Bs)[SC_STRIDE] = (unsigned (*)[SC_STRIDE])(sc_smem + 128 * SC_STRIDE);

    const int tid = threadIdx.x;
    const int w = tid >> 5, lane = tid & 31, g = lane >> 2, t4 = lane & 3;
    const int wm = (w >> 1) * 32, wn = (w & 1) * 64;
    const int h = blockIdx.z;
    const int m0 = blockIdx.y * 128, n0 = blockIdx.x * 128;

    // Load whole 128x64 Q and K tiles (16 independent LDG.128 per thread)
    #pragma unroll
    for (int u = 0; u < 8; u++) {
        int f4 = u * 256 + tid;
        int row = f4 >> 4;            // 0..127
        int c4  = (f4 & 15) * 4;      // 0..60
        float4 qv = *(const float4*)(Q  + (size_t)(m0 + row) * DM + h*DH + c4);
        float4 kv = *(const float4*)(Km + (size_t)(n0 + row) * DM + h*DH + c4);
        *(uint4*)&As[row][c4] = f2tf4(qv);
        *(uint4*)&Bs[row][c4] = f2tf4(kv);
    }
    __syncthreads();

    float4 acc[2][8];
    #pragma unroll
    for (int i = 0; i < 2; i++)
        #pragma unroll
        for (int j = 0; j < 8; j++) acc[i][j] = make_float4(0,0,0,0);

    #pragma unroll
    for (int kc = 0; kc < DH; kc += 8) {
        unsigned bf[8][2];
        #pragma unroll
        for (int j = 0; j < 8; j++) {
            int cn = wn + j*8 + g;
            bf[j][0] = Bs[cn][kc + t4];
            bf[j][1] = Bs[cn][kc + t4 + 4];
        }
        #pragma unroll
        for (int i = 0; i < 2; i++) {
            int rm = wm + i*16 + g;
            unsigned a0 = As[rm][kc+t4],   a1 = As[rm+8][kc+t4];
            unsigned a2 = As[rm][kc+t4+4], a3 = As[rm+8][kc+t4+4];
            #pragma unroll
            for (int j = 0; j < 8; j++)
                mma8(acc[i][j], a0, a1, a2, a3, bf[j][0], bf[j][1]);
        }
    }

    float* out = attn + (size_t)h * SQ * SQ;
    #pragma unroll
    for (int i = 0; i < 2; i++) {
        int mb = m0 + wm + i*16;
        int r0 = mb + g, r1 = mb + g + 8;
        float s0 = 0.f, s1 = 0.f;
        #pragma unroll
        for (int j = 0; j < 8; j++) {
            int n = n0 + wn + j*8 + t4*2;
            int2 mv0 = *(const int2*)(mask + (size_t)r0 * SQ + n);
            int2 mv1 = *(const int2*)(mask + (size_t)r1 * SQ + n);
            float2 o0 = make_float2(mv0.x ? 0.f : __expf(acc[i][j].x),
                                    mv0.y ? 0.f : __expf(acc[i][j].y));
            float2 o1 = make_float2(mv1.x ? 0.f : __expf(acc[i][j].z),
                                    mv1.y ? 0.f : __expf(acc[i][j].w));
            s0 += o0.x + o0.y;
            s1 += o1.x + o1.y;
            *(float2*)(out + (size_t)r0 * SQ + n) = o0;
            *(float2*)(out + (size_t)r1 * SQ + n) = o1;
        }
        s0 += __shfl_xor_sync(0xffffffffu, s0, 1);
        s0 += __shfl_xor_sync(0xffffffffu, s0, 2);
        s1 += __shfl_xor_sync(0xffffffffu, s1, 1);
        s1 += __shfl_xor_sync(0xffffffffu, s1, 2);
        if (t4 == 0) {
            int slot = blockIdx.x * 2 + (wn ? 1 : 0);
            Spart[(size_t)((h << 11) + r0) * 32 + slot] = s0;
            Spart[(size_t)((h << 11) + r1) * 32 + slot] = s1;
        }
    }
}

// ---------------------------------------------------------------------------
__global__ __launch_bounds__(256) void sum_rows(
    const float* __restrict__ Spart, float* __restrict__ S)
{
    int r = blockIdx.x * 256 + threadIdx.x;
    const float4* p = (const float4*)(Spart + (size_t)r * 32);
    float s = 0.f;
    #pragma unroll
    for (int u = 0; u < 8; u++) {
        float4 v = p[u];
        s += (v.x + v.y) + (v.z + v.w);
    }
    S[r] = s;
}

// ---------------------------------------------------------------------------
// av partial (tf32 MMA, NN): K-split 4.  P staged row-major [m][20] with
// vectorized STS; MMA on raw exp; ctx scaled by invS in epilogue; normalized
// attn written back via streaming stores.  128x64 tile, BK=16 ping-pong.
// ---------------------------------------------------------------------------
#define KSPLIT 4
__global__ __launch_bounds__(256) void av_tf32(
    float* __restrict__ attn, const float* __restrict__ V,
    const float* __restrict__ S, OPtr4 parts)
{
    __shared__ unsigned Ps[2][128][20];  // [buf][m][k]
    __shared__ unsigned Vs[2][16][72];   // [buf][k][n]
    const int tid = threadIdx.x;
    const int w = tid >> 5, lane = tid & 31, g = lane >> 2, t4 = lane & 3;
    const int wm = (w >> 1) * 32, wn = (w & 1) * 32;
    const int h = blockIdx.y;
    const int m0 = blockIdx.x * 128;
    const int kb = blockIdx.z * (SQ / KSPLIT);
    float* ctx = parts.o[blockIdx.z];
    const float* Vb = V + (size_t)kb * DM + h * DH;

    const int pr = tid >> 1;
    const int pc = (tid & 1) * 8;
    const int vr = tid >> 4;
    const int vc = (tid & 15) * 4;

    const float invS = 1.0f / S[(h << 11) + m0 + pr];
    float* Prow = attn + (size_t)h * SQ * SQ + (size_t)(m0 + pr) * SQ + kb;

    float4 acc[2][4];
    #pragma unroll
    for (int i = 0; i < 2; i++)
        #pragma unroll
        for (int j = 0; j < 4; j++) acc[i][j] = make_float4(0,0,0,0);

    const int NS = (SQ/KSPLIT) / 16;   // 32 stages

    {
        float4 rp0 = __ldcs((const float4*)(Prow + pc));
        float4 rp1 = __ldcs((const float4*)(Prow + pc + 4));
        float4 rv  = *(const float4*)(Vb + (size_t)vr * DM + vc);
        *(uint4*)&Ps[0][pr][pc]     = f2tf4(rp0);
        *(uint4*)&Ps[0][pr][pc + 4] = f2tf4(rp1);
        *(uint4*)&Vs[0][vr][vc]     = f2tf4(rv);
        float4 w0 = make_float4(rp0.x*invS, rp0.y*invS, rp0.z*invS, rp0.w*invS);
        float4 w1 = make_float4(rp1.x*invS, rp1.y*invS, rp1.z*invS, rp1.w*invS);
        __stcs((float4*)(Prow + pc), w0);
        __stcs((float4*)(Prow + pc + 4), w1);
    }
    float4 qp0 = __ldcs((const float4*)(Prow + 16 + pc));
    float4 qp1 = __ldcs((const float4*)(Prow + 16 + pc + 4));
    float4 qv  = *(const float4*)(Vb + (size_t)(16 + vr) * DM + vc);
    __syncthreads();

    for (int s = 0; s < NS; s++) {
        const int cur = s & 1;
        if (s + 1 < NS) {
            *(uint4*)&Ps[cur ^ 1][pr][pc]     = f2tf4(qp0);
            *(uint4*)&Ps[cur ^ 1][pr][pc + 4] = f2tf4(qp1);
            *(uint4*)&Vs[cur ^ 1][vr][vc]     = f2tf4(qv);
            float4 w0 = make_float4(qp0.x*invS, qp0.y*invS, qp0.z*invS, qp0.w*invS);
            float4 w1 = make_float4(qp1.x*invS, qp1.y*invS, qp1.z*invS, qp1.w*invS);
            __stcs((float4*)(Prow + (s+1)*16 + pc), w0);
            __stcs((float4*)(Prow + (s+1)*16 + pc + 4), w1);
        }
        if (s + 2 < NS) {
            int k = (s + 2) * 16;
            qp0 = __ldcs((const float4*)(Prow + k + pc));
            qp1 = __ldcs((const float4*)(Prow + k + pc + 4));
            qv  = *(const float4*)(Vb + (size_t)(k + vr) * DM + vc);
        }
        unsigned (*Pc)[20] = Ps[cur];
        unsigned (*Vc)[72] = Vs[cur];
        #pragma unroll
        for (int ks = 0; ks < 16; ks += 8) {
            unsigned bf[4][2];
            #pragma unroll
            for (int j = 0; j < 4; j++) {
                int cn = wn + j*8 + g;
                bf[j][0] = Vc[ks + t4][cn];
                bf[j][1] = Vc[ks + t4 + 4][cn];
            }
            #pragma unroll
            for (int i = 0; i < 2; i++) {
                int rm = wm + i*16 + g;
                unsigned a0 = Pc[rm][ks+t4],   a1 = Pc[rm+8][ks+t4];
                unsigned a2 = Pc[rm][ks+t4+4], a3 = Pc[rm+8][ks+t4+4];
                #pragma unroll
                for (int j = 0; j < 4; j++)
                    mma8(acc[i][j], a0, a1, a2, a3, bf[j][0], bf[j][1]);
            }
        }
        __syncthreads();
    }

    #pragma unroll
    for (int i = 0; i < 2; i++) {
        int mb = m0 + wm + i*16;
        float is0 = 1.0f / S[(h << 11) + mb + g];
        float is1 = 1.0f / S[(h << 11) + mb + g + 8];
        #pragma unroll
        for (int j = 0; j < 4; j++) {
            int n = h*DH + wn + j*8 + t4*2;
            *(float2*)(ctx + (size_t)(mb + g)     * DM + n) = make_float2(acc[i][j].x*is0, acc[i][j].y*is0);
            *(float2*)(ctx + (size_t)(mb + g + 8) * DM + n) = make_float2(acc[i][j].z*is1, acc[i][j].w*is1);
        }
    }
}

// ---------------------------------------------------------------------------
extern "C" void kernel_launch(void* const* d_in, const int* in_sizes, int n_in,
                              void* d_out, int out_size)
{
    const float* X    = (const float*)d_in[0];
    const int*   mask = (const int*)d_in[1];
    const float* Wq   = (const float*)d_in[2];
    const float* bq   = (const float*)d_in[3];
    const float* Wk   = (const float*)d_in[4];
    const float* bk   = (const float*)d_in[5];
    const float* Wv   = (const float*)d_in[6];
    const float* bv   = (const float*)d_in[7];
    const float* Wo   = (const float*)d_in[8];
    const float* bo   = (const float*)d_in[9];

    float* out  = (float*)d_out;                 // (S, D)
    float* attn = out + (size_t)SQ * DM;         // (H, S, S)

    float *Qb, *Kb, *Vb, *Cb, *P3, *Sp, *Sb;
    cudaGetSymbolAddress((void**)&Qb, g_Q);
    cudaGetSymbolAddress((void**)&Kb, g_K);
    cudaGetSymbolAddress((void**)&Vb, g_V);
    cudaGetSymbolAddress((void**)&Cb, g_C);
    cudaGetSymbolAddress((void**)&P3, g_P3);
    cudaGetSymbolAddress((void**)&Sp, g_Spart);
    cudaGetSymbolAddress((void**)&Sb, g_S);

    // Allow 69.6 KB dynamic smem for the single-barrier scores kernel.
    cudaFuncSetAttribute(scores_tf32,
        cudaFuncAttributeMaxDynamicSharedMemorySize, SC_SMEM);

    // QKV projections fused into one launch (scale 1/8 folded into Q)
    Proj3 pa;
    pa.W[0]=Wq; pa.W[1]=Wk; pa.W[2]=Wv;
    pa.bias[0]=bq; pa.bias[1]=bk; pa.bias[2]=bv;
    pa.C[0]=Qb; pa.C[1]=Kb; pa.C[2]=Vb;
    pa.scale[0]=0.125f; pa.scale[1]=1.0f; pa.scale[2]=1.0f;
    ASrc ax; ax.p[0]=X; ax.p[1]=nullptr; ax.p[2]=nullptr; ax.p[3]=nullptr;
    proj_tf32<1><<<dim3(8, 16, 3), 256>>>(ax, pa);

    // exp(scores) + partial row sums (single-barrier, dynamic smem)
    scores_tf32<<<dim3(16, 16, 16), 256, SC_SMEM>>>(Qb, Kb, mask, attn, Sp);
    sum_rows<<<NH * SQ / 256, 256>>>(Sp, Sb);

    // av K-split-4: partials into g_C, g_Q, g_K (both dead), g_P3
    OPtr4 op; op.o[0]=Cb; op.o[1]=Qb; op.o[2]=Kb; op.o[3]=P3;
    av_tf32<<<dim3(16, 16, KSPLIT), 256>>>(attn, Vb, Sb, op);

    // out = (p0+p1+p2+p3) @ Wo^T + bo  (reduction fused into A loads)
    Proj3 po;
    po.W[0]=Wo; po.bias[0]=bo; po.C[0]=out; po.scale[0]=1.0f;
    po.W[1]=Wo; po.bias[1]=bo; po.C[1]=out; po.scale[1]=1.0f;
    po.W[2]=Wo; po.bias[2]=bo; po.C[2]=out; po.scale[2]=1.0f;
    ASrc ac; ac.p[0]=Cb; ac.p[1]=Qb; ac.p[2]=Kb; ac.p[3]=P3;
    proj_tf32<4><<<dim3(8, 16, 1), 256>>>(ac, po);
}